// round 16
// baseline (speedup 1.0000x reference)
#include <cuda_runtime.h>
#include <cuda_fp16.h>
#include <math.h>
#include <stdint.h>

#define B_   4
#define T_   2048
#define C_   1024
#define H_   128
#define M_   (B_ * T_)

// chunks of 8 key-tiles; per batch: sum ceil((qt+1)/8) = 80
#define NCHUNK 80

// log2(e)/sqrt(128): folded into Q so softmax is exp2
#define QSCALE (1.4426950408889634f * 0.088388347648318447f)

// ---------------- scratch (fp16, all plain) ----------------
__device__ __half g_Xh[M_ * C_];
__device__ __half g_WTh[3 * H_ * C_];    // W transposed: [y][n][k]
__device__ __half g_Qh[M_ * H_];
__device__ __half g_Kh[M_ * H_];
__device__ __half g_Vh[M_ * H_];
__device__ float g_Opart[4 * NCHUNK * 64 * H_];
__device__ float g_lpart[4 * NCHUNK * 64];
__device__ int   g_cnt[4 * 32];          // per-(b,qt) arrival counters

// ================= helpers =================
__device__ __forceinline__ uint32_t smem_u32(const void* p) {
    uint32_t a;
    asm("{ .reg .u64 t; cvta.to.shared.u64 t, %1; cvt.u32.u64 %0, t; }" : "=r"(a) : "l"(p));
    return a;
}
__device__ __forceinline__ uint32_t pack_h2(float lo, float hi) {
    __half2 h = __floats2half2_rn(lo, hi);
    return *reinterpret_cast<uint32_t*>(&h);
}
__device__ __forceinline__ void ldsm4(uint32_t* r, uint32_t addr) {
    asm volatile("ldmatrix.sync.aligned.m8n8.x4.shared.b16 {%0,%1,%2,%3}, [%4];"
                 : "=r"(r[0]), "=r"(r[1]), "=r"(r[2]), "=r"(r[3]) : "r"(addr));
}
__device__ __forceinline__ void ldsm4t(uint32_t* r, uint32_t addr) {
    asm volatile("ldmatrix.sync.aligned.m8n8.x4.trans.shared.b16 {%0,%1,%2,%3}, [%4];"
                 : "=r"(r[0]), "=r"(r[1]), "=r"(r[2]), "=r"(r[3]) : "r"(addr));
}
__device__ __forceinline__ void mma_f16(float* d, const uint32_t* a, uint32_t b0, uint32_t b1) {
    asm volatile(
        "mma.sync.aligned.m16n8k16.row.col.f32.f16.f16.f32 "
        "{%0,%1,%2,%3}, {%4,%5,%6,%7}, {%8,%9}, {%0,%1,%2,%3};"
        : "+f"(d[0]), "+f"(d[1]), "+f"(d[2]), "+f"(d[3])
        : "r"(a[0]), "r"(a[1]), "r"(a[2]), "r"(a[3]), "r"(b0), "r"(b1));
}
__device__ __forceinline__ void cpasync16(uint32_t dst, const void* src) {
    asm volatile("cp.async.cg.shared.global [%0], [%1], 16;" :: "r"(dst), "l"(src));
}
__device__ __forceinline__ void commitg() {
    asm volatile("cp.async.commit_group;" ::: "memory");
}
__device__ __forceinline__ void waitg0() {
    asm volatile("cp.async.wait_group 0;" ::: "memory");
}
__device__ __forceinline__ void waitg2() {
    asm volatile("cp.async.wait_group 2;" ::: "memory");
}

// ---------------- fused prep: convert X and W^T to fp16; reset counters ---
__global__ __launch_bounds__(256)
void prep_kernel(const float* __restrict__ x,
                 const float* __restrict__ Wq,
                 const float* __restrict__ Wk,
                 const float* __restrict__ Wv)
{
    const int bid = blockIdx.x;
    if (bid < 2048) {
        int g = bid * 256 + threadIdx.x;
        #pragma unroll
        for (int j = 0; j < 4; j++) {
            size_t e = (size_t)g + (size_t)j * 524288;   // float4 index
            float4 v = *(const float4*)(x + e * 4);
            uint2 h = make_uint2(pack_h2(v.x, v.y), pack_h2(v.z, v.w));
            *(uint2*)(g_Xh + e * 4) = h;
        }
    } else {
        if (bid == 2048 && threadIdx.x >= 128) {
            g_cnt[threadIdx.x - 128] = 0;            // reset counters (128 of them)
            return;
        }
        if (threadIdx.x >= 128) return;
        const int wb = bid - 2048;          // 0..47
        const int y  = wb >> 4;
        const int k0 = (wb & 15) * 64;
        const float* W = (y == 0) ? Wq : (y == 1) ? Wk : Wv;
        __half* th = g_WTh + (size_t)y * (H_ * C_);
        const int n = threadIdx.x;
        #pragma unroll
        for (int kk = 0; kk < 64; kk += 8) {
            float v[8];
            #pragma unroll
            for (int j = 0; j < 8; j++) v[j] = W[(size_t)(k0 + kk + j) * H_ + n];
            uint32_t h[4];
            #pragma unroll
            for (int j = 0; j < 4; j++) h[j] = pack_h2(v[j * 2], v[j * 2 + 1]);
            *(uint4*)(th + (size_t)n * C_ + k0 + kk) = make_uint4(h[0], h[1], h[2], h[3]);
        }
    }
}

// ---------------- Projection via fp16 HMMA (R12 config) -------------------
#define PSTG      15360
#define PROJ_SMEM 46080

__global__ __launch_bounds__(256, 2)
void proj_mma_kernel()
{
    extern __shared__ char sm[];
    const uint32_t smb = smem_u32(sm);
    const int tid    = threadIdx.x;
    const int warp   = tid >> 5;
    const int lane   = tid & 31;
    const int warp_m = warp >> 1;
    const int warp_n = warp & 1;
    const int y      = blockIdx.y;
    const int row0   = blockIdx.x * 64;

    const __half* __restrict__ Wh = g_WTh + (size_t)y * (H_ * C_);

    const int lm_row = (lane & 7) + ((lane >> 3) & 1) * 8;
    const int lm_hi  = (lane >> 4) * 16;
    const uint32_t aoff = (uint32_t)((warp_m * 16 + lm_row) * 80 + lm_hi);
    const uint32_t koff = (uint32_t)((warp_n * 64 + (lane & 7)) * 80 + (lane >> 3) * 16);

    auto issue = [&](int stage, int k0) {
        const uint32_t sb = smb + stage * PSTG;
        {
            const int r = tid >> 2, c = tid & 3;
            cpasync16(sb + r * 80 + c * 16, g_Xh + (size_t)(row0 + r) * C_ + k0 + c * 8);
        }
        #pragma unroll
        for (int i = tid; i < 512; i += 256) {
            const int r = i >> 2, c = i & 3;
            cpasync16(sb + 5120 + r * 80 + c * 16, Wh + (size_t)r * C_ + k0 + c * 8);
        }
    };

    issue(0, 0);  commitg();
    issue(1, 32); commitg();
    issue(2, 64); commitg();

    float acc[8][4];
    #pragma unroll
    for (int i = 0; i < 8; i++)
        #pragma unroll
        for (int j = 0; j < 4; j++) acc[i][j] = 0.f;

    for (int kt = 0; kt < 32; kt++) {
        waitg2();
        __syncthreads();
        const uint32_t sb = smb + (kt % 3) * PSTG;

        uint32_t A0[4], A1[4];
        ldsm4(A0, sb + aoff);
        ldsm4(A1, sb + aoff + 32);

        #pragma unroll
        for (int nt = 0; nt < 8; nt++) {
            uint32_t bh[4];
            ldsm4(bh, sb + 5120 + koff + nt * 640);
            mma_f16(acc[nt], A0, bh[0], bh[1]);
            mma_f16(acc[nt], A1, bh[2], bh[3]);
        }
        __syncthreads();
        if (kt + 3 < 32) issue(kt % 3, (kt + 3) * 32);
        commitg();
    }

    // ---- epilogue: fp16 via smem staging (272B rows, coalesced out) ----
    __syncthreads();
    const float sc = (y == 0) ? (float)QSCALE : 1.0f;
    const int r0 = warp_m * 16 + (lane >> 2);
    const int cb = warp_n * 128 + (lane & 3) * 4;
    #pragma unroll
    for (int nt = 0; nt < 8; nt++) {
        const uint32_t cc = (uint32_t)(cb + nt * 16);
        *(uint32_t*)(sm + r0 * 272 + cc)       = pack_h2(acc[nt][0] * sc, acc[nt][1] * sc);
        *(uint32_t*)(sm + (r0 + 8) * 272 + cc) = pack_h2(acc[nt][2] * sc, acc[nt][3] * sc);
    }
    __syncthreads();

    __half* dst = (y == 0) ? g_Qh : (y == 1) ? g_Kh : g_Vh;
    #pragma unroll
    for (int i = tid; i < 1024; i += 256) {
        const int r = i >> 4, c = i & 15;
        uint4 v = *(uint4*)(sm + r * 272 + c * 16);
        *(uint4*)((char*)(dst + (size_t)(row0 + r) * H_) + c * 16) = v;
    }
}

// ---------------- fp16 flash attention, split-K, fused reduction ----------
// S = Q*K (plain). O += P*V (plain). SMEM: K, V tiles 64 x 272B = 34816 B.
// qt 0..7 (single chunk) write out directly. qt 8..31: partials + counter;
// the LAST arriving CTA of each qt reduces all its chunks in-place.
#define TPAD  272
#define SMKH  0
#define SMVH  17408
#define SMTOT 34816

__device__ __forceinline__ void copy_tile(uint32_t smdst, const __half* g, int tid) {
    const char* src = (const char*)g;
    #pragma unroll
    for (int i = tid; i < 1024; i += 128) {
        int r = i >> 4, c = i & 15;
        cpasync16(smdst + r * TPAD + c * 16, src + r * 256 + c * 16);
    }
}

__global__ __launch_bounds__(128, 2)
void attn_kernel(float* __restrict__ out)
{
    extern __shared__ char sm[];
    const uint32_t smb = smem_u32(sm);
    __shared__ int lastFlag;

    const int tid  = threadIdx.x;
    const int warp = tid >> 5;
    const int lane = tid & 31;
    const int b    = blockIdx.y;

    // map blockIdx.x -> (qt, chunk), longest-first
    const int w = (NCHUNK - 1) - (int)blockIdx.x;
    int qt = 0, accum = 0, s = 1;
    #pragma unroll 1
    for (qt = 0; qt < 32; qt++) {
        s = (qt + 8) >> 3;
        if (w < accum + s) break;
        accum += s;
    }
    const int c     = w - accum;
    const int slot  = b * NCHUNK + w;
    const int qbase = qt * 64;
    const int t0    = c * 8;
    const int t1    = min(c * 8 + 8, qt + 1);
    const bool single = (t0 == 0) && (t1 == qt + 1);

    const int lm_row = (lane & 7) + ((lane >> 3) & 1) * 8;
    const int lm_hi  = (lane >> 4) * 16;

    // ---- stage Q tile through K buffer, ldmatrix into registers ----
    {
        const __half* qh = g_Qh + (size_t)(b * T_ + qbase) * H_;
        copy_tile(smb + SMKH, qh, tid);
        commitg(); waitg0();
        __syncthreads();
    }

    uint32_t QA[8][4];
    {
        const uint32_t qoff = (uint32_t)((warp * 16 + lm_row) * TPAD + lm_hi);
        #pragma unroll
        for (int ch = 0; ch < 8; ch++)
            ldsm4(QA[ch], smb + SMKH + qoff + ch * 32);
    }
    __syncthreads();

    float O[16][4];
    #pragma unroll
    for (int i = 0; i < 16; i++)
        #pragma unroll
        for (int j = 0; j < 4; j++) O[i][j] = 0.f;
    float l0 = 0.f, l1 = 0.f;

    const __half* Khg = g_Kh + (size_t)b * T_ * H_;
    const __half* Vhg = g_Vh + (size_t)b * T_ * H_;

    const uint32_t koff = (uint32_t)((lane & 7) * TPAD + (lane >> 3) * 16);
    const uint32_t voff = (uint32_t)(lm_row * TPAD + lm_hi);

    for (int kt = t0; kt < t1; kt++) {
        const int s0 = kt * 64;

        if (kt > t0) __syncthreads();
        copy_tile(smb + SMKH, Khg + (size_t)s0 * H_, tid);
        copy_tile(smb + SMVH, Vhg + (size_t)s0 * H_, tid);
        commitg(); waitg0();
        __syncthreads();

        // ---- S = Q K^T ----
        float Sf[8][4];
        #pragma unroll
        for (int nt = 0; nt < 8; nt++)
            #pragma unroll
            for (int j = 0; j < 4; j++) Sf[nt][j] = 0.f;

        #pragma unroll
        for (int cp = 0; cp < 4; cp++) {
            #pragma unroll
            for (int nt = 0; nt < 8; nt++) {
                uint32_t kh[4];
                ldsm4(kh, smb + SMKH + koff + (uint32_t)(nt * 8 * TPAD) + cp * 64);
                mma_f16(Sf[nt], QA[cp * 2],     kh[0], kh[1]);
                mma_f16(Sf[nt], QA[cp * 2 + 1], kh[2], kh[3]);
            }
        }

        // ---- P = exp2(S), zero-offset, plain fp16 ----
        const bool diag = (kt == qt);
        const int rowg0 = warp * 16 + (lane >> 2);
        uint32_t PH[16];
        #pragma unroll
        for (int nt = 0; nt < 8; nt++) {
            const int colb = nt * 8 + 2 * (lane & 3);
            float e0 = exp2f(Sf[nt][0]);
            float e1 = exp2f(Sf[nt][1]);
            float e2 = exp2f(Sf[nt][2]);
            float e3 = exp2f(Sf[nt][3]);
            if (diag) {
                if (colb     > rowg0)     e0 = 0.f;
                if (colb + 1 > rowg0)     e1 = 0.f;
                if (colb     > rowg0 + 8) e2 = 0.f;
                if (colb + 1 > rowg0 + 8) e3 = 0.f;
            }
            l0 += e0 + e1;
            l1 += e2 + e3;
            PH[nt * 2]     = pack_h2(e0, e1);
            PH[nt * 2 + 1] = pack_h2(e2, e3);
        }

        // ---- O += P V ----
        #pragma unroll
        for (int sc = 0; sc < 4; sc++) {
            const uint32_t* pa = &PH[sc * 4];
            const uint32_t vb = smb + SMVH + voff + (uint32_t)(sc * 16 * TPAD);
            #pragma unroll
            for (int d16 = 0; d16 < 8; d16++) {
                uint32_t vh[4];
                ldsm4t(vh, vb + d16 * 32);
                mma_f16(O[d16 * 2],     pa, vh[0], vh[1]);
                mma_f16(O[d16 * 2 + 1], pa, vh[2], vh[3]);
            }
        }
    }

    // ---- reduce l across the 4 lanes sharing a row ----
    l0 += __shfl_xor_sync(0xffffffffu, l0, 1);
    l0 += __shfl_xor_sync(0xffffffffu, l0, 2);
    l1 += __shfl_xor_sync(0xffffffffu, l1, 1);
    l1 += __shfl_xor_sync(0xffffffffu, l1, 2);

    const int r = lane >> 2, q = lane & 3;

    if (single) {
        const float inv0 = 1.f / l0;
        const float inv1 = 1.f / l1;
        float* o0 = out + ((size_t)(b * T_ + qbase) + warp * 16 + r) * H_ + 2 * q;
        float* o1 = o0 + 8 * H_;
        #pragma unroll
        for (int dt = 0; dt < 16; dt++) {
            *(float2*)(o0 + dt * 8) = make_float2(O[dt][0] * inv0, O[dt][1] * inv0);
            *(float2*)(o1 + dt * 8) = make_float2(O[dt][2] * inv1, O[dt][3] * inv1);
        }
        return;
    }

    // ---- write unnormalized partials ----
    {
        float* o0 = g_Opart + (size_t)slot * (64 * H_) + (warp * 16 + r) * H_ + 2 * q;
        float* o1 = o0 + 8 * H_;
        #pragma unroll
        for (int dt = 0; dt < 16; dt++) {
            *(float2*)(o0 + dt * 8) = make_float2(O[dt][0], O[dt][1]);
            *(float2*)(o1 + dt * 8) = make_float2(O[dt][2], O[dt][3]);
        }
        if (q == 0) {
            g_lpart[slot * 64 + warp * 16 + r]     = l0;
            g_lpart[slot * 64 + warp * 16 + r + 8] = l1;
        }
    }

    // ---- last-CTA-wins reduction ----
    __threadfence();
    __syncthreads();
    if (tid == 0) {
        int v = atomicAdd(&g_cnt[b * 32 + qt], 1);
        lastFlag = (v == s - 1);
    }
    __syncthreads();
    if (!lastFlag) return;

    const int base = b * NCHUNK + accum;   // slot of chunk 0 for this qt
    float* invp = (float*)sm;              // K/V tiles no longer needed
    if (tid < 64) {
        float l = 0.f;
        #pragma unroll 4
        for (int j = 0; j < s; j++) l += g_lpart[(base + j) * 64 + tid];
        invp[tid] = 1.f / l;
    }
    __syncthreads();

    #pragma unroll 1
    for (int e4 = tid; e4 < 2048; e4 += 128) {
        const int rr = e4 >> 5;
        float4 o = make_float4(0.f, 0.f, 0.f, 0.f);
        #pragma unroll 4
        for (int j = 0; j < s; j++) {
            float4 p = *(const float4*)(g_Opart + (size_t)(base + j) * (64 * H_) + e4 * 4);
            o.x += p.x; o.y += p.y; o.z += p.z; o.w += p.w;
        }
        const float iv = invp[rr];
        o.x *= iv; o.y *= iv; o.z *= iv; o.w *= iv;
        *(float4*)(out + ((size_t)(b * T_ + qt * 64) << 7) + e4 * 4) = o;
    }
}

// ---------------- launcher ----------------------------------------
extern "C" void kernel_launch(void* const* d_in, const int* in_sizes, int n_in,
                              void* d_out, int out_size)
{
    const float* x  = (const float*)d_in[0];
    const float* Wq = (const float*)d_in[1];
    const float* Wk = (const float*)d_in[2];
    const float* Wv = (const float*)d_in[3];
    float* out = (float*)d_out;

    prep_kernel<<<2096, 256>>>(x, Wq, Wk, Wv);

    cudaFuncSetAttribute(proj_mma_kernel,
                         cudaFuncAttributeMaxDynamicSharedMemorySize, PROJ_SMEM);
    proj_mma_kernel<<<dim3(128, 3), 256, PROJ_SMEM>>>();

    cudaFuncSetAttribute(attn_kernel,
                         cudaFuncAttributeMaxDynamicSharedMemorySize, SMTOT);
    attn_kernel<<<dim3(NCHUNK, 4), 128, SMTOT>>>(out);
}

// round 17
// speedup vs baseline: 1.0966x; 1.0966x over previous
#include <cuda_runtime.h>
#include <cuda_fp16.h>
#include <math.h>
#include <stdint.h>

#define B_   4
#define T_   2048
#define C_   1024
#define H_   128
#define M_   (B_ * T_)

// chunks of 8 key-tiles; per batch: sum ceil((qt+1)/8) = 80
#define NCHUNK 80

// log2(e)/sqrt(128): folded into Q so softmax is exp2
#define QSCALE (1.4426950408889634f * 0.088388347648318447f)

// ---------------- scratch (fp16, all plain) ----------------
__device__ __half g_Xh[M_ * C_];
__device__ __half g_WTh[3 * H_ * C_];    // W transposed: [y][n][k]
__device__ __half g_Qh[M_ * H_];
__device__ __half g_Kh[M_ * H_];
__device__ __half g_Vh[M_ * H_];
__device__ float g_Opart[4 * NCHUNK * 64 * H_];
__device__ float g_lpart[4 * NCHUNK * 64];

// ================= helpers =================
__device__ __forceinline__ uint32_t smem_u32(const void* p) {
    uint32_t a;
    asm("{ .reg .u64 t; cvta.to.shared.u64 t, %1; cvt.u32.u64 %0, t; }" : "=r"(a) : "l"(p));
    return a;
}
__device__ __forceinline__ uint32_t pack_h2(float lo, float hi) {
    __half2 h = __floats2half2_rn(lo, hi);
    return *reinterpret_cast<uint32_t*>(&h);
}
__device__ __forceinline__ void ldsm4(uint32_t* r, uint32_t addr) {
    asm volatile("ldmatrix.sync.aligned.m8n8.x4.shared.b16 {%0,%1,%2,%3}, [%4];"
                 : "=r"(r[0]), "=r"(r[1]), "=r"(r[2]), "=r"(r[3]) : "r"(addr));
}
__device__ __forceinline__ void ldsm4t(uint32_t* r, uint32_t addr) {
    asm volatile("ldmatrix.sync.aligned.m8n8.x4.trans.shared.b16 {%0,%1,%2,%3}, [%4];"
                 : "=r"(r[0]), "=r"(r[1]), "=r"(r[2]), "=r"(r[3]) : "r"(addr));
}
__device__ __forceinline__ void mma_f16(float* d, const uint32_t* a, uint32_t b0, uint32_t b1) {
    asm volatile(
        "mma.sync.aligned.m16n8k16.row.col.f32.f16.f16.f32 "
        "{%0,%1,%2,%3}, {%4,%5,%6,%7}, {%8,%9}, {%0,%1,%2,%3};"
        : "+f"(d[0]), "+f"(d[1]), "+f"(d[2]), "+f"(d[3])
        : "r"(a[0]), "r"(a[1]), "r"(a[2]), "r"(a[3]), "r"(b0), "r"(b1));
}
__device__ __forceinline__ void cpasync16(uint32_t dst, const void* src) {
    asm volatile("cp.async.cg.shared.global [%0], [%1], 16;" :: "r"(dst), "l"(src));
}
__device__ __forceinline__ void commitg() {
    asm volatile("cp.async.commit_group;" ::: "memory");
}
__device__ __forceinline__ void waitg0() {
    asm volatile("cp.async.wait_group 0;" ::: "memory");
}
__device__ __forceinline__ void waitg2() {
    asm volatile("cp.async.wait_group 2;" ::: "memory");
}

// ---------------- fused prep: convert X and W^T to fp16 -------------------
__global__ __launch_bounds__(256)
void prep_kernel(const float* __restrict__ x,
                 const float* __restrict__ Wq,
                 const float* __restrict__ Wk,
                 const float* __restrict__ Wv)
{
    const int bid = blockIdx.x;
    if (bid < 2048) {
        int g = bid * 256 + threadIdx.x;
        // load all 4 float4 first (MLP=4), then convert+store
        float4 v[4];
        #pragma unroll
        for (int j = 0; j < 4; j++) {
            size_t e = (size_t)g + (size_t)j * 524288;   // float4 index
            v[j] = *(const float4*)(x + e * 4);
        }
        #pragma unroll
        for (int j = 0; j < 4; j++) {
            size_t e = (size_t)g + (size_t)j * 524288;
            uint2 h = make_uint2(pack_h2(v[j].x, v[j].y), pack_h2(v[j].z, v[j].w));
            *(uint2*)(g_Xh + e * 4) = h;
        }
    } else {
        if (threadIdx.x >= 128) return;
        const int wb = bid - 2048;          // 0..47
        const int y  = wb >> 4;
        const int k0 = (wb & 15) * 64;
        const float* W = (y == 0) ? Wq : (y == 1) ? Wk : Wv;
        __half* th = g_WTh + (size_t)y * (H_ * C_);
        const int n = threadIdx.x;
        #pragma unroll
        for (int kk = 0; kk < 64; kk += 8) {
            float v[8];
            #pragma unroll
            for (int j = 0; j < 8; j++) v[j] = W[(size_t)(k0 + kk + j) * H_ + n];
            uint32_t h[4];
            #pragma unroll
            for (int j = 0; j < 4; j++) h[j] = pack_h2(v[j * 2], v[j * 2 + 1]);
            *(uint4*)(th + (size_t)n * C_ + k0 + kk) = make_uint4(h[0], h[1], h[2], h[3]);
        }
    }
}

// ---------------- Projection via fp16 HMMA, 1-term, 3-stage pipeline ------
#define PSTG      15360
#define PROJ_SMEM 46080

__global__ __launch_bounds__(256, 2)
void proj_mma_kernel()
{
    extern __shared__ char sm[];
    const uint32_t smb = smem_u32(sm);
    const int tid    = threadIdx.x;
    const int warp   = tid >> 5;
    const int lane   = tid & 31;
    const int warp_m = warp >> 1;
    const int warp_n = warp & 1;
    const int y      = blockIdx.y;
    const int row0   = blockIdx.x * 64;

    const __half* __restrict__ Wh = g_WTh + (size_t)y * (H_ * C_);

    const int lm_row = (lane & 7) + ((lane >> 3) & 1) * 8;
    const int lm_hi  = (lane >> 4) * 16;
    const uint32_t aoff = (uint32_t)((warp_m * 16 + lm_row) * 80 + lm_hi);
    const uint32_t koff = (uint32_t)((warp_n * 64 + (lane & 7)) * 80 + (lane >> 3) * 16);

    auto issue = [&](int stage, int k0) {
        const uint32_t sb = smb + stage * PSTG;
        {
            const int r = tid >> 2, c = tid & 3;
            cpasync16(sb + r * 80 + c * 16, g_Xh + (size_t)(row0 + r) * C_ + k0 + c * 8);
        }
        #pragma unroll
        for (int i = tid; i < 512; i += 256) {
            const int r = i >> 2, c = i & 3;
            cpasync16(sb + 5120 + r * 80 + c * 16, Wh + (size_t)r * C_ + k0 + c * 8);
        }
    };

    issue(0, 0);  commitg();
    issue(1, 32); commitg();
    issue(2, 64); commitg();

    float acc[8][4];
    #pragma unroll
    for (int i = 0; i < 8; i++)
        #pragma unroll
        for (int j = 0; j < 4; j++) acc[i][j] = 0.f;

    for (int kt = 0; kt < 32; kt++) {
        waitg2();
        __syncthreads();
        const uint32_t sb = smb + (kt % 3) * PSTG;

        uint32_t A0[4], A1[4];
        ldsm4(A0, sb + aoff);
        ldsm4(A1, sb + aoff + 32);

        #pragma unroll
        for (int nt = 0; nt < 8; nt++) {
            uint32_t bh[4];
            ldsm4(bh, sb + 5120 + koff + nt * 640);
            mma_f16(acc[nt], A0, bh[0], bh[1]);
            mma_f16(acc[nt], A1, bh[2], bh[3]);
        }
        __syncthreads();
        if (kt + 3 < 32) issue(kt % 3, (kt + 3) * 32);
        commitg();
    }

    // ---- epilogue: fp16 via smem staging (272B rows, coalesced out) ----
    __syncthreads();
    const float sc = (y == 0) ? (float)QSCALE : 1.0f;
    const int r0 = warp_m * 16 + (lane >> 2);
    const int cb = warp_n * 128 + (lane & 3) * 4;
    #pragma unroll
    for (int nt = 0; nt < 8; nt++) {
        const uint32_t cc = (uint32_t)(cb + nt * 16);
        *(uint32_t*)(sm + r0 * 272 + cc)       = pack_h2(acc[nt][0] * sc, acc[nt][1] * sc);
        *(uint32_t*)(sm + (r0 + 8) * 272 + cc) = pack_h2(acc[nt][2] * sc, acc[nt][3] * sc);
    }
    __syncthreads();

    __half* dst = (y == 0) ? g_Qh : (y == 1) ? g_Kh : g_Vh;
    #pragma unroll
    for (int i = tid; i < 1024; i += 256) {
        const int r = i >> 4, c = i & 15;
        uint4 v = *(uint4*)(sm + r * 272 + c * 16);
        *(uint4*)((char*)(dst + (size_t)(row0 + r) * H_) + c * 16) = v;
    }
}

// ---------------- fp16 flash attention, split-K (chunks of 8) -------------
// S = Q*K (plain). O += P*V (plain). SMEM: K, V tiles 64 x 272B = 34816 B.
// Single-chunk q-tiles (qt 0..7) normalize and write out directly.
#define TPAD  272
#define SMKH  0
#define SMVH  17408
#define SMTOT 34816

__device__ __forceinline__ void copy_tile(uint32_t smdst, const __half* g, int tid) {
    const char* src = (const char*)g;
    #pragma unroll
    for (int i = tid; i < 1024; i += 128) {
        int r = i >> 4, c = i & 15;
        cpasync16(smdst + r * TPAD + c * 16, src + r * 256 + c * 16);
    }
}

__global__ __launch_bounds__(128, 2)
void attn_kernel(float* __restrict__ out)
{
    extern __shared__ char sm[];
    const uint32_t smb = smem_u32(sm);

    const int tid  = threadIdx.x;
    const int warp = tid >> 5;
    const int lane = tid & 31;
    const int b    = blockIdx.y;

    // map blockIdx.x -> (qt, chunk), longest-first
    const int w = (NCHUNK - 1) - (int)blockIdx.x;
    int qt = 0, accum = 0, s = 1;
    #pragma unroll 1
    for (qt = 0; qt < 32; qt++) {
        s = (qt + 8) >> 3;
        if (w < accum + s) break;
        accum += s;
    }
    const int c     = w - accum;
    const int slot  = b * NCHUNK + w;
    const int qbase = qt * 64;
    const int t0    = c * 8;
    const int t1    = min(c * 8 + 8, qt + 1);
    const bool single = (t0 == 0) && (t1 == qt + 1);

    const int lm_row = (lane & 7) + ((lane >> 3) & 1) * 8;
    const int lm_hi  = (lane >> 4) * 16;

    // ---- stage Q tile through K buffer, ldmatrix into registers ----
    {
        const __half* qh = g_Qh + (size_t)(b * T_ + qbase) * H_;
        copy_tile(smb + SMKH, qh, tid);
        commitg(); waitg0();
        __syncthreads();
    }

    uint32_t QA[8][4];
    {
        const uint32_t qoff = (uint32_t)((warp * 16 + lm_row) * TPAD + lm_hi);
        #pragma unroll
        for (int ch = 0; ch < 8; ch++)
            ldsm4(QA[ch], smb + SMKH + qoff + ch * 32);
    }
    __syncthreads();

    float O[16][4];
    #pragma unroll
    for (int i = 0; i < 16; i++)
        #pragma unroll
        for (int j = 0; j < 4; j++) O[i][j] = 0.f;
    float l0 = 0.f, l1 = 0.f;

    const __half* Khg = g_Kh + (size_t)b * T_ * H_;
    const __half* Vhg = g_Vh + (size_t)b * T_ * H_;

    const uint32_t koff = (uint32_t)((lane & 7) * TPAD + (lane >> 3) * 16);
    const uint32_t voff = (uint32_t)(lm_row * TPAD + lm_hi);

    for (int kt = t0; kt < t1; kt++) {
        const int s0 = kt * 64;

        if (kt > t0) __syncthreads();
        copy_tile(smb + SMKH, Khg + (size_t)s0 * H_, tid);
        copy_tile(smb + SMVH, Vhg + (size_t)s0 * H_, tid);
        commitg(); waitg0();
        __syncthreads();

        // ---- S = Q K^T ----
        float Sf[8][4];
        #pragma unroll
        for (int nt = 0; nt < 8; nt++)
            #pragma unroll
            for (int j = 0; j < 4; j++) Sf[nt][j] = 0.f;

        #pragma unroll
        for (int cp = 0; cp < 4; cp++) {
            #pragma unroll
            for (int nt = 0; nt < 8; nt++) {
                uint32_t kh[4];
                ldsm4(kh, smb + SMKH + koff + (uint32_t)(nt * 8 * TPAD) + cp * 64);
                mma_f16(Sf[nt], QA[cp * 2],     kh[0], kh[1]);
                mma_f16(Sf[nt], QA[cp * 2 + 1], kh[2], kh[3]);
            }
        }

        // ---- P = exp2(S), zero-offset, plain fp16 ----
        const bool diag = (kt == qt);
        const int rowg0 = warp * 16 + (lane >> 2);
        uint32_t PH[16];
        #pragma unroll
        for (int nt = 0; nt < 8; nt++) {
            const int colb = nt * 8 + 2 * (lane & 3);
            float e0 = exp2f(Sf[nt][0]);
            float e1 = exp2f(Sf[nt][1]);
            float e2 = exp2f(Sf[nt][2]);
            float e3 = exp2f(Sf[nt][3]);
            if (diag) {
                if (colb     > rowg0)     e0 = 0.f;
                if (colb + 1 > rowg0)     e1 = 0.f;
                if (colb     > rowg0 + 8) e2 = 0.f;
                if (colb + 1 > rowg0 + 8) e3 = 0.f;
            }
            l0 += e0 + e1;
            l1 += e2 + e3;
            PH[nt * 2]     = pack_h2(e0, e1);
            PH[nt * 2 + 1] = pack_h2(e2, e3);
        }

        // ---- O += P V ----
        #pragma unroll
        for (int sc = 0; sc < 4; sc++) {
            const uint32_t* pa = &PH[sc * 4];
            const uint32_t vb = smb + SMVH + voff + (uint32_t)(sc * 16 * TPAD);
            #pragma unroll
            for (int d16 = 0; d16 < 8; d16++) {
                uint32_t vh[4];
                ldsm4t(vh, vb + d16 * 32);
                mma_f16(O[d16 * 2],     pa, vh[0], vh[1]);
                mma_f16(O[d16 * 2 + 1], pa, vh[2], vh[3]);
            }
        }
    }

    // ---- reduce l across the 4 lanes sharing a row ----
    l0 += __shfl_xor_sync(0xffffffffu, l0, 1);
    l0 += __shfl_xor_sync(0xffffffffu, l0, 2);
    l1 += __shfl_xor_sync(0xffffffffu, l1, 1);
    l1 += __shfl_xor_sync(0xffffffffu, l1, 2);

    const int r = lane >> 2, q = lane & 3;

    if (single) {
        const float inv0 = 1.f / l0;
        const float inv1 = 1.f / l1;
        float* o0 = out + ((size_t)(b * T_ + qbase) + warp * 16 + r) * H_ + 2 * q;
        float* o1 = o0 + 8 * H_;
        #pragma unroll
        for (int dt = 0; dt < 16; dt++) {
            *(float2*)(o0 + dt * 8) = make_float2(O[dt][0] * inv0, O[dt][1] * inv0);
            *(float2*)(o1 + dt * 8) = make_float2(O[dt][2] * inv1, O[dt][3] * inv1);
        }
    } else {
        float* o0 = g_Opart + (size_t)slot * (64 * H_) + (warp * 16 + r) * H_ + 2 * q;
        float* o1 = o0 + 8 * H_;
        #pragma unroll
        for (int dt = 0; dt < 16; dt++) {
            *(float2*)(o0 + dt * 8) = make_float2(O[dt][0], O[dt][1]);
            *(float2*)(o1 + dt * 8) = make_float2(O[dt][2], O[dt][3]);
        }
        if (q == 0) {
            g_lpart[slot * 64 + warp * 16 + r]     = l0;
            g_lpart[slot * 64 + warp * 16 + r + 8] = l1;
        }
    }
}

// ---------------- combine split-K partials (qt 8..31 only) ----------------
// grid (24, B_, 8): x -> qt-8, z -> eighth of the 2048 float4 elements.
__global__ __launch_bounds__(256)
void reduce_kernel(float* __restrict__ out)
{
    const int qt = 8 + blockIdx.x;
    const int b  = blockIdx.y;
    const int z  = blockIdx.z;
    const int tid = threadIdx.x;

    const int s = (qt + 8) >> 3;
    int cum = 8;   // qt 0..7 contribute 1 chunk each
    #pragma unroll 1
    for (int q = 8; q < qt; q++) cum += (q + 8) >> 3;
    const int base = b * NCHUNK + cum;

    __shared__ float inv[64];
    if (tid < 64) {
        float l = 0.f;
        #pragma unroll 4
        for (int j = 0; j < s; j++) l += g_lpart[(base + j) * 64 + tid];
        inv[tid] = 1.f / l;
    }
    __syncthreads();

    // this CTA handles 256 float4 elements: [z*256, z*256+256)
    const int e4 = z * 256 + tid;
    const int rr = e4 >> 5;
    float4 o = make_float4(0.f, 0.f, 0.f, 0.f);
    #pragma unroll 4
    for (int j = 0; j < s; j++) {
        float4 p = *(const float4*)(g_Opart + (size_t)(base + j) * (64 * H_) + e4 * 4);
        o.x += p.x; o.y += p.y; o.z += p.z; o.w += p.w;
    }
    const float iv = inv[rr];
    o.x *= iv; o.y *= iv; o.z *= iv; o.w *= iv;
    *(float4*)(out + ((size_t)(b * T_ + qt * 64) << 7) + e4 * 4) = o;
}

// ---------------- launcher ----------------------------------------
extern "C" void kernel_launch(void* const* d_in, const int* in_sizes, int n_in,
                              void* d_out, int out_size)
{
    const float* x  = (const float*)d_in[0];
    const float* Wq = (const float*)d_in[1];
    const float* Wk = (const float*)d_in[2];
    const float* Wv = (const float*)d_in[3];
    float* out = (float*)d_out;

    prep_kernel<<<2096, 256>>>(x, Wq, Wk, Wv);

    cudaFuncSetAttribute(proj_mma_kernel,
                         cudaFuncAttributeMaxDynamicSharedMemorySize, PROJ_SMEM);
    proj_mma_kernel<<<dim3(128, 3), 256, PROJ_SMEM>>>();

    cudaFuncSetAttribute(attn_kernel,
                         cudaFuncAttributeMaxDynamicSharedMemorySize, SMTOT);
    attn_kernel<<<dim3(NCHUNK, 4), 128, SMTOT>>>(out);

    reduce_kernel<<<dim3(24, 4, 8), 256>>>(out);
}